// round 1
// baseline (speedup 1.0000x reference)
#include <cuda_runtime.h>

#define NN 50000
#define EE 800000
#define FF 64
#define NITER 34

// ---- device scratch (allocation-free rule: __device__ globals) ----
__device__ int2  g_edge[EE];        // packed (src, __float_as_int(w_norm)), CSR-ordered by dst
__device__ float g_deg[NN];         // sum of raw edge weights into each dst
__device__ int   g_cnt[NN];         // histogram / scatter cursor
__device__ int   g_rowptr[NN + 1];  // CSR row pointers (by dst)
__device__ float g_buf0[NN * FF];
__device__ float g_buf1[NN * FF];

__global__ void k_init() {
    int i = blockIdx.x * blockDim.x + threadIdx.x;
    if (i < NN) { g_deg[i] = 0.0f; g_cnt[i] = 0; }
}

__global__ void k_hist(const float* __restrict__ e, const int* __restrict__ dst) {
    int i = blockIdx.x * blockDim.x + threadIdx.x;
    if (i < EE) {
        int d = dst[i];
        atomicAdd(&g_deg[d], e[i]);
        atomicAdd(&g_cnt[d], 1);
    }
}

// Exclusive prefix sum of g_cnt -> g_rowptr, single block of 1024 threads.
// Also resets g_cnt to 0 for reuse as the scatter cursor.
__global__ void k_scan() {
    __shared__ int part[1024];
    const int CH = (NN + 1023) / 1024;  // 49 elements per thread
    int t = threadIdx.x;
    int start = t * CH;

    int s = 0;
    for (int k = 0; k < CH; k++) {
        int idx = start + k;
        if (idx < NN) s += g_cnt[idx];
    }
    part[t] = s;
    __syncthreads();

    // Hillis-Steele inclusive scan over the 1024 partials
    for (int off = 1; off < 1024; off <<= 1) {
        int v = 0;
        if (t >= off) v = part[t - off];
        __syncthreads();
        if (t >= off) part[t] += v;
        __syncthreads();
    }

    int base = (t == 0) ? 0 : part[t - 1];
    for (int k = 0; k < CH; k++) {
        int idx = start + k;
        if (idx < NN) {
            g_rowptr[idx] = base;
            base += g_cnt[idx];
            g_cnt[idx] = 0;  // reset for scatter pass
        }
    }
    if (t == 1023) g_rowptr[NN] = part[1023];  // == EE
}

__global__ void k_scatter(const float* __restrict__ e,
                          const int* __restrict__ src,
                          const int* __restrict__ dst) {
    int i = blockIdx.x * blockDim.x + threadIdx.x;
    if (i < EE) {
        int d = dst[i];
        int pos = g_rowptr[d] + atomicAdd(&g_cnt[d], 1);
        float w = e[i] / fmaxf(g_deg[d], 1e-12f);
        g_edge[pos] = make_int2(src[i], __float_as_int(w));
    }
}

// One damped propagation step: xout = 0.5 * (A_hat xin) + 0.5 * b
// Thread layout: tid -> (node = tid>>6, feature = tid&63). Warp lanes cover 32
// consecutive features of the SAME node => every gathered x row-segment is a
// fully coalesced 128B line; edge metadata is one broadcast int2 per warp.
__global__ void __launch_bounds__(256) k_iter(const float* __restrict__ xin,
                                              float* __restrict__ xout,
                                              const float* __restrict__ bsrc) {
    int t = blockIdx.x * blockDim.x + threadIdx.x;
    if (t >= NN * FF) return;
    int node = t >> 6;
    int f = t & (FF - 1);

    int j    = g_rowptr[node];
    int jend = g_rowptr[node + 1];

    float acc = 0.0f;
    // unroll x2 for memory-level parallelism
    for (; j + 2 <= jend; j += 2) {
        int2 e0 = g_edge[j];
        int2 e1 = g_edge[j + 1];
        float x0 = __ldg(&xin[e0.x * FF + f]);
        float x1 = __ldg(&xin[e1.x * FF + f]);
        acc = fmaf(__int_as_float(e0.y), x0, acc);
        acc = fmaf(__int_as_float(e1.y), x1, acc);
    }
    if (j < jend) {
        int2 e0 = g_edge[j];
        acc = fmaf(__int_as_float(e0.y), __ldg(&xin[e0.x * FF + f]), acc);
    }

    xout[t] = 0.5f * acc + 0.5f * bsrc[t];
}

extern "C" void kernel_launch(void* const* d_in, const int* in_sizes, int n_in,
                              void* d_out, int out_size) {
    (void)in_sizes; (void)n_in; (void)out_size;
    const float* x   = (const float*)d_in[0];
    const float* e   = (const float*)d_in[1];
    const float* b   = (const float*)d_in[2];
    const int*   src = (const int*)d_in[3];
    const int*   dst = (const int*)d_in[4];
    float* out = (float*)d_out;

    // --- build dst-CSR with normalized weights (runs inside the graph) ---
    k_init<<<(NN + 255) / 256, 256>>>();
    k_hist<<<(EE + 255) / 256, 256>>>(e, dst);
    k_scan<<<1, 1024>>>();
    k_scatter<<<(EE + 255) / 256, 256>>>(e, src, dst);

    // --- fixed-count damped iterations (contraction 0.5 => 34 iters is
    //     numerically converged to the fp32 fixed point) ---
    float *b0, *b1;
    cudaGetSymbolAddress((void**)&b0, g_buf0);
    cudaGetSymbolAddress((void**)&b1, g_buf1);

    const int grid = (NN * FF + 255) / 256;
    const float* cur = x;   // iteration 0 reads the input directly
    float* nxt = b0;
    for (int it = 0; it < NITER; ++it) {
        float* o = (it == NITER - 1) ? out : nxt;
        k_iter<<<grid, 256>>>(cur, o, b);
        cur = o;
        nxt = (nxt == b0) ? b1 : b0;
    }
}

// round 2
// speedup vs baseline: 2.1246x; 2.1246x over previous
#include <cuda_runtime.h>

#define NN 50000
#define EE 800000
#define FF 64
#define NITER 20   // contraction factor 0.5 => truncation error 0.5^20 ~ 1e-6 rms

// ---- device scratch (allocation-free rule: __device__ globals) ----
__device__ int2  g_edge[EE];        // packed (src, __float_as_int(w_norm)), CSR-ordered by dst
__device__ float g_deg[NN];         // sum of raw edge weights into each dst
__device__ int   g_cnt[NN];         // histogram / scatter cursor
__device__ int   g_rowptr[NN + 1];  // CSR row pointers (by dst)
__device__ float g_buf0[NN * FF];
__device__ float g_buf1[NN * FF];

__global__ void k_init() {
    int i = blockIdx.x * blockDim.x + threadIdx.x;
    if (i < NN) { g_deg[i] = 0.0f; g_cnt[i] = 0; }
}

__global__ void k_hist(const float* __restrict__ e, const int* __restrict__ dst) {
    int i = blockIdx.x * blockDim.x + threadIdx.x;
    if (i < EE) {
        int d = dst[i];
        atomicAdd(&g_deg[d], e[i]);
        atomicAdd(&g_cnt[d], 1);
    }
}

// Exclusive prefix sum of g_cnt -> g_rowptr, single block of 1024 threads.
// Also resets g_cnt to 0 for reuse as the scatter cursor.
__global__ void k_scan() {
    __shared__ int part[1024];
    const int CH = (NN + 1023) / 1024;  // 49 elements per thread
    int t = threadIdx.x;
    int start = t * CH;

    int s = 0;
    for (int k = 0; k < CH; k++) {
        int idx = start + k;
        if (idx < NN) s += g_cnt[idx];
    }
    part[t] = s;
    __syncthreads();

    for (int off = 1; off < 1024; off <<= 1) {
        int v = 0;
        if (t >= off) v = part[t - off];
        __syncthreads();
        if (t >= off) part[t] += v;
        __syncthreads();
    }

    int base = (t == 0) ? 0 : part[t - 1];
    for (int k = 0; k < CH; k++) {
        int idx = start + k;
        if (idx < NN) {
            g_rowptr[idx] = base;
            base += g_cnt[idx];
            g_cnt[idx] = 0;  // reset for scatter pass
        }
    }
    if (t == 1023) g_rowptr[NN] = part[1023];  // == EE
}

__global__ void k_scatter(const float* __restrict__ e,
                          const int* __restrict__ src,
                          const int* __restrict__ dst) {
    int i = blockIdx.x * blockDim.x + threadIdx.x;
    if (i < EE) {
        int d = dst[i];
        int pos = g_rowptr[d] + atomicAdd(&g_cnt[d], 1);
        float w = e[i] / fmaxf(g_deg[d], 1e-12f);
        g_edge[pos] = make_int2(src[i], __float_as_int(w));
    }
}

// One damped propagation step: xout = 0.5 * (A_hat xin) + 0.5 * b
// Thread layout: thread = (node, 4-feature chunk). 16 lanes cover one node's
// 64 features; every gathered x row-segment is a coalesced 256B group of
// float4 loads. 4-way unroll => 4 independent 16B gathers in flight per
// thread to cover ~240cyc L2 latency.
__global__ void __launch_bounds__(256) k_iter(const float4* __restrict__ xin,
                                              float4* __restrict__ xout,
                                              const float4* __restrict__ bsrc) {
    int t = blockIdx.x * blockDim.x + threadIdx.x;
    if (t >= NN * (FF / 4)) return;
    int node = t >> 4;       // FF/4 = 16 chunks per node
    int q = t & 15;

    int j    = __ldg(&g_rowptr[node]);
    int jend = __ldg(&g_rowptr[node + 1]);

    float4 acc = make_float4(0.f, 0.f, 0.f, 0.f);

    // 4-way unrolled main loop
    for (; j + 4 <= jend; j += 4) {
        int2 e0 = g_edge[j];
        int2 e1 = g_edge[j + 1];
        int2 e2 = g_edge[j + 2];
        int2 e3 = g_edge[j + 3];
        float4 x0 = __ldg(&xin[e0.x * 16 + q]);
        float4 x1 = __ldg(&xin[e1.x * 16 + q]);
        float4 x2 = __ldg(&xin[e2.x * 16 + q]);
        float4 x3 = __ldg(&xin[e3.x * 16 + q]);
        float w0 = __int_as_float(e0.y);
        float w1 = __int_as_float(e1.y);
        float w2 = __int_as_float(e2.y);
        float w3 = __int_as_float(e3.y);
        acc.x = fmaf(w0, x0.x, acc.x); acc.y = fmaf(w0, x0.y, acc.y);
        acc.z = fmaf(w0, x0.z, acc.z); acc.w = fmaf(w0, x0.w, acc.w);
        acc.x = fmaf(w1, x1.x, acc.x); acc.y = fmaf(w1, x1.y, acc.y);
        acc.z = fmaf(w1, x1.z, acc.z); acc.w = fmaf(w1, x1.w, acc.w);
        acc.x = fmaf(w2, x2.x, acc.x); acc.y = fmaf(w2, x2.y, acc.y);
        acc.z = fmaf(w2, x2.z, acc.z); acc.w = fmaf(w2, x2.w, acc.w);
        acc.x = fmaf(w3, x3.x, acc.x); acc.y = fmaf(w3, x3.y, acc.y);
        acc.z = fmaf(w3, x3.z, acc.z); acc.w = fmaf(w3, x3.w, acc.w);
    }
    for (; j < jend; ++j) {
        int2 e0 = g_edge[j];
        float4 x0 = __ldg(&xin[e0.x * 16 + q]);
        float w0 = __int_as_float(e0.y);
        acc.x = fmaf(w0, x0.x, acc.x); acc.y = fmaf(w0, x0.y, acc.y);
        acc.z = fmaf(w0, x0.z, acc.z); acc.w = fmaf(w0, x0.w, acc.w);
    }

    float4 bb = __ldg(&bsrc[t]);
    float4 o;
    o.x = 0.5f * acc.x + 0.5f * bb.x;
    o.y = 0.5f * acc.y + 0.5f * bb.y;
    o.z = 0.5f * acc.z + 0.5f * bb.z;
    o.w = 0.5f * acc.w + 0.5f * bb.w;
    xout[t] = o;
}

extern "C" void kernel_launch(void* const* d_in, const int* in_sizes, int n_in,
                              void* d_out, int out_size) {
    (void)in_sizes; (void)n_in; (void)out_size;
    const float* x   = (const float*)d_in[0];
    const float* e   = (const float*)d_in[1];
    const float* b   = (const float*)d_in[2];
    const int*   src = (const int*)d_in[3];
    const int*   dst = (const int*)d_in[4];
    float* out = (float*)d_out;

    // --- build dst-CSR with normalized weights (runs inside the graph) ---
    k_init<<<(NN + 255) / 256, 256>>>();
    k_hist<<<(EE + 255) / 256, 256>>>(e, dst);
    k_scan<<<1, 1024>>>();
    k_scatter<<<(EE + 255) / 256, 256>>>(e, src, dst);

    // --- fixed-count damped iterations ---
    float *b0, *b1;
    cudaGetSymbolAddress((void**)&b0, g_buf0);
    cudaGetSymbolAddress((void**)&b1, g_buf1);

    const int grid = (NN * (FF / 4) + 255) / 256;
    const float* cur = x;   // iteration 0 reads the input directly
    float* nxt = b0;
    for (int it = 0; it < NITER; ++it) {
        float* o = (it == NITER - 1) ? out : nxt;
        k_iter<<<grid, 256>>>((const float4*)cur, (float4*)o, (const float4*)b);
        cur = o;
        nxt = (nxt == b0) ? b1 : b0;
    }
}

// round 4
// speedup vs baseline: 2.5472x; 1.1989x over previous
#include <cuda_runtime.h>
#include <cuda_fp16.h>

#define NN 50000
#define EE 800000
#define FF 64
#define NITER_H 16   // fp16-storage iterations
// + 2 fp32 iterations at the end => 18 total; 0.5^18 truncation ~ 4e-6

// ---- device scratch (allocation-free rule: __device__ globals) ----
__device__ int2  g_edge[EE];        // packed (src, w_norm bits), CSR-ordered by dst
__device__ float g_deg[NN];
__device__ int   g_cnt[NN];
__device__ int   g_rowptr[NN + 1];
__device__ uint4 g_half0[NN * 8];   // fp16 iterate: 8 halves per uint4, 8 uint4 per node
__device__ uint4 g_half1[NN * 8];
__device__ float g_buf0[NN * FF];   // fp32 iterate for final steps

__global__ void k_init() {
    int i = blockIdx.x * blockDim.x + threadIdx.x;
    if (i < NN) { g_deg[i] = 0.0f; g_cnt[i] = 0; }
}

__global__ void k_hist(const float* __restrict__ e, const int* __restrict__ dst) {
    int i = blockIdx.x * blockDim.x + threadIdx.x;
    if (i < EE) {
        int d = dst[i];
        atomicAdd(&g_deg[d], e[i]);
        atomicAdd(&g_cnt[d], 1);
    }
}

// Exclusive prefix sum of g_cnt -> g_rowptr, single block of 1024 threads.
__global__ void k_scan() {
    __shared__ int part[1024];
    const int CH = (NN + 1023) / 1024;
    int t = threadIdx.x;
    int start = t * CH;

    int s = 0;
    for (int k = 0; k < CH; k++) {
        int idx = start + k;
        if (idx < NN) s += g_cnt[idx];
    }
    part[t] = s;
    __syncthreads();

    for (int off = 1; off < 1024; off <<= 1) {
        int v = 0;
        if (t >= off) v = part[t - off];
        __syncthreads();
        if (t >= off) part[t] += v;
        __syncthreads();
    }

    int base = (t == 0) ? 0 : part[t - 1];
    for (int k = 0; k < CH; k++) {
        int idx = start + k;
        if (idx < NN) {
            g_rowptr[idx] = base;
            base += g_cnt[idx];
            g_cnt[idx] = 0;
        }
    }
    if (t == 1023) g_rowptr[NN] = part[1023];
}

__global__ void k_scatter(const float* __restrict__ e,
                          const int* __restrict__ src,
                          const int* __restrict__ dst) {
    int i = blockIdx.x * blockDim.x + threadIdx.x;
    if (i < EE) {
        int d = dst[i];
        int pos = g_rowptr[d] + atomicAdd(&g_cnt[d], 1);
        float w = e[i] / fmaxf(g_deg[d], 1e-12f);
        g_edge[pos] = make_int2(src[i], __float_as_int(w));
    }
}

// Convert fp32 x -> fp16 iterate buffer. t indexes 8-feature chunks.
__global__ void k_tohalf(const float4* __restrict__ xin, uint4* __restrict__ xh) {
    int t = blockIdx.x * blockDim.x + threadIdx.x;
    if (t >= NN * 8) return;
    float4 a = xin[t * 2];
    float4 c = xin[t * 2 + 1];
    __half2 h0 = __floats2half2_rn(a.x, a.y);
    __half2 h1 = __floats2half2_rn(a.z, a.w);
    __half2 h2 = __floats2half2_rn(c.x, c.y);
    __half2 h3 = __floats2half2_rn(c.z, c.w);
    uint4 o;
    o.x = *(unsigned*)&h0; o.y = *(unsigned*)&h1;
    o.z = *(unsigned*)&h2; o.w = *(unsigned*)&h3;
    xh[t] = o;
}

// fp16 -> fp16 damped step. Thread = (node, 8-feature chunk); 8 lanes per node.
// Gathered row-chunk = one 16B uint4 (8 halves). Accumulate in fp32.
__global__ void __launch_bounds__(256) k_iter_h(const uint4* __restrict__ xin,
                                                uint4* __restrict__ xout,
                                                const float4* __restrict__ b4) {
    int t = blockIdx.x * blockDim.x + threadIdx.x;
    if (t >= NN * 8) return;
    int node = t >> 3;
    int q = t & 7;

    int j    = __ldg(&g_rowptr[node]);
    int jend = __ldg(&g_rowptr[node + 1]);

    float2 a0 = {0.f, 0.f}, a1 = {0.f, 0.f}, a2 = {0.f, 0.f}, a3 = {0.f, 0.f};

#define EDGE_H(EV)                                                         \
    {                                                                      \
        float w = __int_as_float((EV).y);                                  \
        uint4 hv = __ldg(&xin[(EV).x * 8 + q]);                            \
        float2 f0 = __half22float2(*(__half2*)&hv.x);                      \
        float2 f1 = __half22float2(*(__half2*)&hv.y);                      \
        float2 f2 = __half22float2(*(__half2*)&hv.z);                      \
        float2 f3 = __half22float2(*(__half2*)&hv.w);                      \
        a0.x = fmaf(w, f0.x, a0.x); a0.y = fmaf(w, f0.y, a0.y);            \
        a1.x = fmaf(w, f1.x, a1.x); a1.y = fmaf(w, f1.y, a1.y);            \
        a2.x = fmaf(w, f2.x, a2.x); a2.y = fmaf(w, f2.y, a2.y);            \
        a3.x = fmaf(w, f3.x, a3.x); a3.y = fmaf(w, f3.y, a3.y);            \
    }

    for (; j + 4 <= jend; j += 4) {
        int2 e0 = g_edge[j];
        int2 e1 = g_edge[j + 1];
        int2 e2 = g_edge[j + 2];
        int2 e3 = g_edge[j + 3];
        EDGE_H(e0); EDGE_H(e1); EDGE_H(e2); EDGE_H(e3);
    }
    for (; j < jend; ++j) {
        int2 e0 = g_edge[j];
        EDGE_H(e0);
    }

    float4 bA = __ldg(&b4[t * 2]);
    float4 bB = __ldg(&b4[t * 2 + 1]);
    __half2 o0 = __floats2half2_rn(0.5f * a0.x + 0.5f * bA.x, 0.5f * a0.y + 0.5f * bA.y);
    __half2 o1 = __floats2half2_rn(0.5f * a1.x + 0.5f * bA.z, 0.5f * a1.y + 0.5f * bA.w);
    __half2 o2 = __floats2half2_rn(0.5f * a2.x + 0.5f * bB.x, 0.5f * a2.y + 0.5f * bB.y);
    __half2 o3 = __floats2half2_rn(0.5f * a3.x + 0.5f * bB.z, 0.5f * a3.y + 0.5f * bB.w);
    uint4 o;
    o.x = *(unsigned*)&o0; o.y = *(unsigned*)&o1;
    o.z = *(unsigned*)&o2; o.w = *(unsigned*)&o3;
    xout[t] = o;
}

// fp16 -> fp32 damped step (first of the two precision-recovery iterations).
__global__ void __launch_bounds__(256) k_iter_h2f(const uint4* __restrict__ xin,
                                                  float4* __restrict__ xout,
                                                  const float4* __restrict__ b4) {
    int t = blockIdx.x * blockDim.x + threadIdx.x;
    if (t >= NN * 8) return;
    int node = t >> 3;
    int q = t & 7;

    int j    = __ldg(&g_rowptr[node]);
    int jend = __ldg(&g_rowptr[node + 1]);

    float2 a0 = {0.f, 0.f}, a1 = {0.f, 0.f}, a2 = {0.f, 0.f}, a3 = {0.f, 0.f};

    for (; j + 4 <= jend; j += 4) {
        int2 e0 = g_edge[j];
        int2 e1 = g_edge[j + 1];
        int2 e2 = g_edge[j + 2];
        int2 e3 = g_edge[j + 3];
        EDGE_H(e0); EDGE_H(e1); EDGE_H(e2); EDGE_H(e3);
    }
    for (; j < jend; ++j) {
        int2 e0 = g_edge[j];
        EDGE_H(e0);
    }

    float4 bA = __ldg(&b4[t * 2]);
    float4 bB = __ldg(&b4[t * 2 + 1]);
    float4 oA, oB;
    oA.x = 0.5f * a0.x + 0.5f * bA.x; oA.y = 0.5f * a0.y + 0.5f * bA.y;
    oA.z = 0.5f * a1.x + 0.5f * bA.z; oA.w = 0.5f * a1.y + 0.5f * bA.w;
    oB.x = 0.5f * a2.x + 0.5f * bB.x; oB.y = 0.5f * a2.y + 0.5f * bB.y;
    oB.z = 0.5f * a3.x + 0.5f * bB.z; oB.w = 0.5f * a3.y + 0.5f * bB.w;
    xout[t * 2] = oA;
    xout[t * 2 + 1] = oB;
}

// fp32 -> fp32 damped step (final iteration, writes d_out).
__global__ void __launch_bounds__(256) k_iter_f(const float4* __restrict__ xin,
                                                float4* __restrict__ xout,
                                                const float4* __restrict__ b4) {
    int t = blockIdx.x * blockDim.x + threadIdx.x;
    if (t >= NN * 16) return;
    int node = t >> 4;
    int q = t & 15;

    int j    = __ldg(&g_rowptr[node]);
    int jend = __ldg(&g_rowptr[node + 1]);

    float4 acc = make_float4(0.f, 0.f, 0.f, 0.f);
    for (; j + 4 <= jend; j += 4) {
        int2 e0 = g_edge[j];
        int2 e1 = g_edge[j + 1];
        int2 e2 = g_edge[j + 2];
        int2 e3 = g_edge[j + 3];
        float4 x0 = __ldg(&xin[e0.x * 16 + q]);
        float4 x1 = __ldg(&xin[e1.x * 16 + q]);
        float4 x2 = __ldg(&xin[e2.x * 16 + q]);
        float4 x3 = __ldg(&xin[e3.x * 16 + q]);
        float w0 = __int_as_float(e0.y), w1 = __int_as_float(e1.y);
        float w2 = __int_as_float(e2.y), w3 = __int_as_float(e3.y);
        acc.x = fmaf(w0, x0.x, acc.x); acc.y = fmaf(w0, x0.y, acc.y);
        acc.z = fmaf(w0, x0.z, acc.z); acc.w = fmaf(w0, x0.w, acc.w);
        acc.x = fmaf(w1, x1.x, acc.x); acc.y = fmaf(w1, x1.y, acc.y);
        acc.z = fmaf(w1, x1.z, acc.z); acc.w = fmaf(w1, x1.w, acc.w);
        acc.x = fmaf(w2, x2.x, acc.x); acc.y = fmaf(w2, x2.y, acc.y);
        acc.z = fmaf(w2, x2.z, acc.z); acc.w = fmaf(w2, x2.w, acc.w);
        acc.x = fmaf(w3, x3.x, acc.x); acc.y = fmaf(w3, x3.y, acc.y);
        acc.z = fmaf(w3, x3.z, acc.z); acc.w = fmaf(w3, x3.w, acc.w);
    }
    for (; j < jend; ++j) {
        int2 e0 = g_edge[j];
        float4 x0 = __ldg(&xin[e0.x * 16 + q]);
        float w0 = __int_as_float(e0.y);
        acc.x = fmaf(w0, x0.x, acc.x); acc.y = fmaf(w0, x0.y, acc.y);
        acc.z = fmaf(w0, x0.z, acc.z); acc.w = fmaf(w0, x0.w, acc.w);
    }

    float4 bb = __ldg(&b4[t]);
    float4 o;
    o.x = 0.5f * acc.x + 0.5f * bb.x;
    o.y = 0.5f * acc.y + 0.5f * bb.y;
    o.z = 0.5f * acc.z + 0.5f * bb.z;
    o.w = 0.5f * acc.w + 0.5f * bb.w;
    xout[t] = o;
}

extern "C" void kernel_launch(void* const* d_in, const int* in_sizes, int n_in,
                              void* d_out, int out_size) {
    (void)in_sizes; (void)n_in; (void)out_size;
    const float* x   = (const float*)d_in[0];
    const float* e   = (const float*)d_in[1];
    const float* b   = (const float*)d_in[2];
    const int*   src = (const int*)d_in[3];
    const int*   dst = (const int*)d_in[4];
    float* out = (float*)d_out;

    // --- build dst-CSR with normalized weights ---
    k_init<<<(NN + 255) / 256, 256>>>();
    k_hist<<<(EE + 255) / 256, 256>>>(e, dst);
    k_scan<<<1, 1024>>>();
    k_scatter<<<(EE + 255) / 256, 256>>>(e, src, dst);

    uint4 *h0, *h1; float* f0;
    cudaGetSymbolAddress((void**)&h0, g_half0);
    cudaGetSymbolAddress((void**)&h1, g_half1);
    cudaGetSymbolAddress((void**)&f0, g_buf0);

    const int gridH = (NN * 8 + 255) / 256;
    const int gridF = (NN * 16 + 255) / 256;

    // x -> fp16
    k_tohalf<<<gridH, 256>>>((const float4*)x, h0);

    // fp16 iterations
    uint4* cur = h0;
    uint4* nxt = h1;
    for (int it = 0; it < NITER_H; ++it) {
        k_iter_h<<<gridH, 256>>>(cur, nxt, (const float4*)b);
        uint4* tmp = cur; cur = nxt; nxt = tmp;
    }

    // two fp32 precision-recovery iterations; last writes d_out
    k_iter_h2f<<<gridH, 256>>>(cur, (float4*)f0, (const float4*)b);
    k_iter_f<<<gridF, 256>>>((const float4*)f0, (float4*)out, (const float4*)b);
}